// round 9
// baseline (speedup 1.0000x reference)
#include <cuda_runtime.h>
#include <cuda_fp16.h>
#include <math.h>
#include <stdint.h>

#define N_NODES 32768
#define N_EDGES 524288
#define FT_IN   256
#define HID     128
#define DHID    129        // HID+1
#define BATCH   64
#define NPB     512        // N_NODES / BATCH
#define EPSV    1e-7f

// ---------------- scratch (device globals; no runtime allocation) ----------
__device__ __half2 g_zh[N_NODES * (HID / 2)];  // z in fp16 (gather table)
__device__ float g_ssrc[N_NODES];
__device__ float g_sdst[N_NODES];
__device__ float g_t[N_NODES * HID];      // tangent vec between layers (gelu'd)
__device__ float g_h2[N_NODES * DHID];    // after layer-2 (hyperboloid)
// CSR by dst (built once per call, reused by both layers)
__device__ int   g_off[N_NODES + 1];
__device__ int   g_cur[N_NODES];          // counts, then scatter cursors
__device__ int   g_csrc[N_EDGES];         // src ids grouped by dst

// ---------------- helpers --------------------------------------------------
__device__ __forceinline__ float warp_sum(float v) {
    #pragma unroll
    for (int o = 16; o > 0; o >>= 1) v += __shfl_xor_sync(0xFFFFFFFFu, v, o);
    return v;
}
__device__ __forceinline__ float gelu_tanh(float t) {
    float t3 = t * t * t;
    return 0.5f * t * (1.0f + tanhf(0.7978845608028654f * (t + 0.044715f * t3)));
}
__device__ __forceinline__ uint32_t f2tf32(float f) {
    uint32_t r;
    asm("cvt.rna.tf32.f32 %0, %1;" : "=r"(r) : "f"(f));
    return r;
}
__device__ __forceinline__ void mma_tf32(float c[4], uint32_t a0, uint32_t a1,
                                         uint32_t a2, uint32_t a3,
                                         uint32_t b0, uint32_t b1) {
    asm volatile(
        "mma.sync.aligned.m16n8k8.row.col.f32.tf32.tf32.f32 "
        "{%0,%1,%2,%3}, {%4,%5,%6,%7}, {%8,%9}, {%0,%1,%2,%3};"
        : "+f"(c[0]), "+f"(c[1]), "+f"(c[2]), "+f"(c[3])
        : "r"(a0), "r"(a1), "r"(a2), "r"(a3), "r"(b0), "r"(b1));
}

// ---------------- CSR build -------------------------------------------------
__global__ void k_zero() {
    int i = blockIdx.x * blockDim.x + threadIdx.x;
    if (i < N_NODES) g_cur[i] = 0;
}
__global__ void k_hist(const int* __restrict__ ei) {
    int i = blockIdx.x * blockDim.x + threadIdx.x;     // i < N_EDGES/4
    int4 v = ((const int4*)ei)[i];
    atomicAdd(&g_cur[v.x], 1);
    atomicAdd(&g_cur[v.y], 1);
    atomicAdd(&g_cur[v.z], 1);
    atomicAdd(&g_cur[v.w], 1);
}
// single block, 1024 threads, 32 counts each: exclusive scan -> g_off, g_cur
__global__ void k_scan() {
    __shared__ int bsum[1024];
    int t = threadIdx.x;
    int base = t * 32;
    int local[32];
    int s = 0;
    #pragma unroll
    for (int i = 0; i < 32; i++) { local[i] = g_cur[base + i]; s += local[i]; }
    bsum[t] = s;
    __syncthreads();
    #pragma unroll
    for (int off = 1; off < 1024; off <<= 1) {
        int v = (t >= off) ? bsum[t - off] : 0;
        __syncthreads();
        bsum[t] += v;
        __syncthreads();
    }
    int run = bsum[t] - s;           // exclusive prefix for this thread's chunk
    #pragma unroll
    for (int i = 0; i < 32; i++) {
        g_off[base + i] = run;
        g_cur[base + i] = run;
        run += local[i];
    }
    if (t == 1023) g_off[N_NODES] = run;
}
__global__ void k_scatter(const int* __restrict__ ei) {
    int i = blockIdx.x * blockDim.x + threadIdx.x;     // i < N_EDGES/4
    int4 d = ((const int4*)ei)[i];
    int4 s = ((const int4*)(ei + N_EDGES))[i];
    int p;
    p = atomicAdd(&g_cur[d.x], 1); g_csrc[p] = s.x;
    p = atomicAdd(&g_cur[d.y], 1); g_csrc[p] = s.y;
    p = atomicAdd(&g_cur[d.z], 1); g_csrc[p] = s.z;
    p = atomicAdd(&g_cur[d.w], 1); g_csrc[p] = s.w;
}

// ---------- TF32 MMA GEMM + fused attention scores -------------------------
// LOG=true : A on hyperboloid (lda cols, col0 = time), Z = diag(r)*(Asp@W)+b,
//            r = acosh(max(A0,1+e))/max(||Asp||,e)   (layer 1, A = x)
// LOG=false: A already tangent (g_t, 128 cols), Z = A@W + b (layer 2)
// Emits Z in fp16 (g_zh) and g_ssrc = Z·a_src, g_sdst = Z·a_dst (fp32 exact).
// BM=128, BN=128(HID), BK=16. 256 threads = 8 warps, warp tile 32x64.
template <int K, bool LOG>
__global__ void k_gemm(const float* __restrict__ A, int lda,
                       const float* __restrict__ W,
                       const float* __restrict__ bias,
                       const float* __restrict__ asrc,
                       const float* __restrict__ adst) {
    __shared__ uint32_t As[128][20];   // [m][k] tf32 bits, padded
    __shared__ uint32_t Bs[16][136];   // [k][n] tf32 bits, padded
    __shared__ float    Rs[128];
    __shared__ float    Ssrc[128];
    __shared__ float    Sdst[128];
    const float* Ax = LOG ? A : g_t;
    int t    = threadIdx.x;
    int m0   = blockIdx.x * 128;
    int lane = t & 31, warp = t >> 5;
    int wm = (warp & 3) * 32;          // warp row offset
    int wn = (warp >> 2) * 64;         // warp col offset
    int g  = lane >> 2, tg = lane & 3;

    if (t < 128) { Ssrc[t] = 0.f; Sdst[t] = 0.f; }

    float acc[2][8][4];
    #pragma unroll
    for (int mi = 0; mi < 2; mi++)
        #pragma unroll
        for (int nj = 0; nj < 8; nj++)
            #pragma unroll
            for (int q = 0; q < 4; q++) acc[mi][nj][q] = 0.f;

    int la_m = t >> 1, la_k = (t & 1) * 8;
    int lb_k = t >> 4, lb_n = (t & 15) * 8;
    float ssq = 0.f;

    for (int k0 = 0; k0 < K; k0 += 16) {
        const float* ap = LOG
            ? Ax + (size_t)(m0 + la_m) * lda + 1 + k0 + la_k
            : Ax + (size_t)(m0 + la_m) * HID + k0 + la_k;
        #pragma unroll
        for (int i = 0; i < 8; i++) {
            float v = ap[i];
            if (LOG) ssq += v * v;
            As[la_m][la_k + i] = f2tf32(v);
        }
        const float* bp = W + (size_t)(k0 + lb_k) * HID + lb_n;
        #pragma unroll
        for (int i = 0; i < 8; i++) Bs[lb_k][lb_n + i] = f2tf32(bp[i]);
        __syncthreads();
        #pragma unroll
        for (int ks = 0; ks < 2; ks++) {
            int kk = ks * 8;
            uint32_t bf0[8], bf1[8];
            #pragma unroll
            for (int nj = 0; nj < 8; nj++) {
                bf0[nj] = Bs[kk + tg][wn + nj * 8 + g];
                bf1[nj] = Bs[kk + tg + 4][wn + nj * 8 + g];
            }
            #pragma unroll
            for (int mi = 0; mi < 2; mi++) {
                int r = wm + mi * 16 + g;
                uint32_t a0 = As[r][kk + tg];
                uint32_t a1 = As[r + 8][kk + tg];
                uint32_t a2 = As[r][kk + tg + 4];
                uint32_t a3 = As[r + 8][kk + tg + 4];
                #pragma unroll
                for (int nj = 0; nj < 8; nj++)
                    mma_tf32(acc[mi][nj], a0, a1, a2, a3, bf0[nj], bf1[nj]);
            }
        }
        __syncthreads();
    }
    if (LOG) {
        // per-row logmap0 scale (threads t, t^1 hold halves of row t>>1)
        float tot = ssq + __shfl_xor_sync(0xFFFFFFFFu, ssq, 1);
        if ((t & 1) == 0) {
            float x0 = fmaxf(Ax[(size_t)(m0 + la_m) * lda], 1.0f + EPSV);
            Rs[la_m] = acoshf(x0) / fmaxf(sqrtf(tot), EPSV);
        }
        __syncthreads();
    }

    // epilogue: z = r*acc + bias (fp32), scores fp32, store z as half2
    int   rows[4] = { wm + g, wm + g + 8, wm + 16 + g, wm + 24 + g };
    float rv[4];
    #pragma unroll
    for (int i = 0; i < 4; i++) rv[i] = LOG ? Rs[rows[i]] : 1.0f;
    float ps[4] = {0.f, 0.f, 0.f, 0.f};
    float pd[4] = {0.f, 0.f, 0.f, 0.f};
    #pragma unroll
    for (int nj = 0; nj < 8; nj++) {
        int c = wn + nj * 8 + 2 * tg;
        float b0v = bias[c], b1v = bias[c + 1];
        float s0 = asrc[c], s1 = asrc[c + 1];
        float d0 = adst[c], d1 = adst[c + 1];
        #pragma unroll
        for (int mi = 0; mi < 2; mi++) {
            float r0v = rv[mi * 2], r1v = rv[mi * 2 + 1];
            float v00 = r0v * acc[mi][nj][0] + b0v;
            float v01 = r0v * acc[mi][nj][1] + b1v;
            float v10 = r1v * acc[mi][nj][2] + b0v;
            float v11 = r1v * acc[mi][nj][3] + b1v;
            g_zh[(size_t)(m0 + rows[mi * 2]) * (HID / 2) + (c >> 1)]
                = __floats2half2_rn(v00, v01);
            g_zh[(size_t)(m0 + rows[mi * 2 + 1]) * (HID / 2) + (c >> 1)]
                = __floats2half2_rn(v10, v11);
            ps[mi * 2]     += v00 * s0 + v01 * s1;
            ps[mi * 2 + 1] += v10 * s0 + v11 * s1;
            pd[mi * 2]     += v00 * d0 + v01 * d1;
            pd[mi * 2 + 1] += v10 * d0 + v11 * d1;
        }
    }
    #pragma unroll
    for (int i = 0; i < 4; i++) {
        atomicAdd(&Ssrc[rows[i]], ps[i]);
        atomicAdd(&Sdst[rows[i]], pd[i]);
    }
    __syncthreads();
    if (t < 128) {
        g_ssrc[m0 + t] = Ssrc[t];
        g_sdst[m0 + t] = Sdst[t];
    }
}

// ---------------- fused GAT aggregation + post-processing -------------------
// One warp per node; lane l owns channels [4l, 4l+4).
// Per 32-edge chunk: coalesced csrc load + per-lane score/exp, then shfl
// distributes (src, w); z-gathers are the only per-edge memory ops.
// No softmax max-shift (scores O(0.01), exp cannot overflow).
//  MODE 0: g = gelu(logmap0(projx(expmap0(u))))  -> g_t  (tangent; the
//          expmap0 for layer-2 input cancels against its logmap0 exactly)
//  MODE 1: h = projx(expmap0(u))                 -> g_h2
template <int MODE>
__global__ void k_gat() {
    int node = blockIdx.x * 8 + (threadIdx.x >> 5);
    int lane = threadIdx.x & 31;
    int beg = g_off[node], end = g_off[node + 1];
    float sdst = g_sdst[node];
    float4 acc = make_float4(0.f, 0.f, 0.f, 0.f);
    float denp = 0.f;

    for (int base = beg; base < end; base += 32) {
        int m = end - base; if (m > 32) m = 32;
        int sid = 0; float w = 0.f;
        if (lane < m) {
            sid = g_csrc[base + lane];
            float sc = sdst + g_ssrc[sid];
            sc = (sc > 0.f) ? sc : 0.2f * sc;
            w = __expf(sc);
        }
        denp += w;
        int j = 0;
        for (; j + 4 <= m; j += 4) {
            int s0 = __shfl_sync(0xFFFFFFFFu, sid, j);
            int s1 = __shfl_sync(0xFFFFFFFFu, sid, j + 1);
            int s2 = __shfl_sync(0xFFFFFFFFu, sid, j + 2);
            int s3 = __shfl_sync(0xFFFFFFFFu, sid, j + 3);
            float w0 = __shfl_sync(0xFFFFFFFFu, w, j);
            float w1 = __shfl_sync(0xFFFFFFFFu, w, j + 1);
            float w2 = __shfl_sync(0xFFFFFFFFu, w, j + 2);
            float w3 = __shfl_sync(0xFFFFFFFFu, w, j + 3);
            uint2 p0 = ((const uint2*)(g_zh + (size_t)s0 * (HID / 2)))[lane];
            uint2 p1 = ((const uint2*)(g_zh + (size_t)s1 * (HID / 2)))[lane];
            uint2 p2 = ((const uint2*)(g_zh + (size_t)s2 * (HID / 2)))[lane];
            uint2 p3 = ((const uint2*)(g_zh + (size_t)s3 * (HID / 2)))[lane];
            float2 a0 = __half22float2(*(const __half2*)&p0.x);
            float2 b0 = __half22float2(*(const __half2*)&p0.y);
            float2 a1 = __half22float2(*(const __half2*)&p1.x);
            float2 b1 = __half22float2(*(const __half2*)&p1.y);
            float2 a2 = __half22float2(*(const __half2*)&p2.x);
            float2 b2 = __half22float2(*(const __half2*)&p2.y);
            float2 a3 = __half22float2(*(const __half2*)&p3.x);
            float2 b3 = __half22float2(*(const __half2*)&p3.y);
            acc.x += w0 * a0.x + w1 * a1.x + w2 * a2.x + w3 * a3.x;
            acc.y += w0 * a0.y + w1 * a1.y + w2 * a2.y + w3 * a3.y;
            acc.z += w0 * b0.x + w1 * b1.x + w2 * b2.x + w3 * b3.x;
            acc.w += w0 * b0.y + w1 * b1.y + w2 * b2.y + w3 * b3.y;
        }
        for (; j < m; j++) {
            int sj = __shfl_sync(0xFFFFFFFFu, sid, j);
            float wj = __shfl_sync(0xFFFFFFFFu, w, j);
            uint2 pj = ((const uint2*)(g_zh + (size_t)sj * (HID / 2)))[lane];
            float2 aj = __half22float2(*(const __half2*)&pj.x);
            float2 bj = __half22float2(*(const __half2*)&pj.y);
            acc.x += wj * aj.x; acc.y += wj * aj.y;
            acc.z += wj * bj.x; acc.w += wj * bj.y;
        }
    }
    float den = warp_sum(denp);

    float dn = fmaxf(den, EPSV);
    float u[4] = { acc.x / dn, acc.y / dn, acc.z / dn, acc.w / dn };
    float ss = u[0]*u[0] + u[1]*u[1] + u[2]*u[2] + u[3]*u[3];
    ss = warp_sum(ss);
    float n    = sqrtf(ss);
    float coef = (n < EPSV) ? 1.0f : (sinhf(n) / n);      // expmap0 spatial

    float xs_n2 = coef * coef * ss;
    if (MODE == 1) {
        float* hr = g_h2 + (size_t)node * DHID;
        if (lane == 0) hr[0] = sqrtf(1.0f + xs_n2);
        #pragma unroll
        for (int q = 0; q < 4; q++) hr[1 + lane * 4 + q] = coef * u[q];
        return;
    }
    // MODE 0: projx -> logmap0 -> gelu, store tangent vector (no expmap0:
    // it cancels against layer-2's logmap0)
    float x0p = sqrtf(1.0f + xs_n2);
    float xsn = sqrtf(xs_n2);
    float sc2 = acoshf(fmaxf(x0p, 1.0f + EPSV)) / fmaxf(xsn, EPSV);
    float4 gv;
    gv.x = gelu_tanh(sc2 * coef * u[0]);
    gv.y = gelu_tanh(sc2 * coef * u[1]);
    gv.z = gelu_tanh(sc2 * coef * u[2]);
    gv.w = gelu_tanh(sc2 * coef * u[3]);
    ((float4*)(g_t + (size_t)node * HID))[lane] = gv;
}

// --------- fused centroid + head (one block per batch graph) ----------------
// Block b (512 threads): coalesced column-sum of h2[b*512 .. b*512+511][:],
// centroid normalize, then the W_lin head on node b*512's row.
__global__ void k_readout(const float* __restrict__ Wl,
                          const float* __restrict__ lin_scale,
                          float* __restrict__ out) {
    int b = blockIdx.x;
    int t = threadIdx.x;
    __shared__ float ave[DHID];
    __shared__ float gsh[DHID];
    __shared__ float red[3];
    if (t < DHID) ave[t] = 0.f;
    __syncthreads();

    const float* base = g_h2 + (size_t)b * NPB * DHID;
    float lsum = 0.f; int lcol = -1;
    for (int idx = t; idx < NPB * DHID; idx += 512) {
        int col = idx % DHID;
        float v = base[idx];
        if (col == lcol) { lsum += v; }
        else {
            if (lcol >= 0) atomicAdd(&ave[lcol], lsum);
            lcol = col; lsum = v;
        }
    }
    if (lcol >= 0) atomicAdd(&ave[lcol], lsum);
    if (t < DHID) gsh[t] = base[t];          // node b*512 row (for head)
    __syncthreads();

    if (t == 0) {
        float inner = 0.f;
        #pragma unroll 4
        for (int c = 1; c < DHID; c++) inner += ave[c] * ave[c];
        float a0 = ave[0];
        inner = inner * (1.0f / ((float)NPB * (float)NPB));
        a0 = a0 * (1.0f / (float)NPB);
        inner -= a0 * a0;
        red[0] = sqrtf(fmaxf(-inner, 1e-8f));
    }
    __syncthreads();
    if (t < DHID)
        out[BATCH * DHID + b * DHID + t] =
            ave[t] * (1.0f / (float)NPB) / red[0];

    // ---- head ----
    float y = 0.f;
    if (t < DHID) {
        #pragma unroll 4
        for (int k = 0; k < DHID; k++) y += gsh[k] * Wl[k * DHID + t];
    }
    if (t == 0) { red[1] = y; red[2] = 0.f; }
    __syncthreads();
    if (t >= 1 && t < DHID) atomicAdd(&red[2], y * y);
    __syncthreads();
    if (t < DHID) {
        float tt  = 1.0f / (1.0f + expf(-red[1])) * lin_scale[0] + 1.1f;
        float fac = sqrtf((tt * tt - 1.0f) / fmaxf(red[2], 1e-8f));
        out[b * DHID + t] = (t == 0) ? tt : y * fac;
    }
}

// ---------------- launch ----------------------------------------------------
extern "C" void kernel_launch(void* const* d_in, const int* in_sizes, int n_in,
                              void* d_out, int out_size) {
    int idx = 0;
    const float* x  = (const float*)d_in[idx++];   // (32768, 257)
    const int*   ei = (const int*)d_in[idx++];     // (2, 524288)
    if (idx < n_in && in_sizes[idx] == 1) idx++;   // batch_size scalar, if present
    const float* W1  = (const float*)d_in[idx++];
    const float* b1  = (const float*)d_in[idx++];
    const float* a1s = (const float*)d_in[idx++];
    const float* a1d = (const float*)d_in[idx++];
    const float* W2  = (const float*)d_in[idx++];
    const float* b2  = (const float*)d_in[idx++];
    const float* a2s = (const float*)d_in[idx++];
    const float* a2d = (const float*)d_in[idx++];
    const float* Wl  = (const float*)d_in[idx++];
    const float* ls  = (const float*)d_in[idx++];
    float* out = (float*)d_out;

    // side stream + events, created once (first call is the uncaptured
    // correctness run; capture replays see only the recorded DAG)
    static cudaStream_t s2 = 0;
    static cudaEvent_t evFork = 0, evCsr = 0;
    if (!s2) {
        cudaStreamCreateWithFlags(&s2, cudaStreamNonBlocking);
        cudaEventCreateWithFlags(&evFork, cudaEventDisableTiming);
        cudaEventCreateWithFlags(&evCsr, cudaEventDisableTiming);
    }

    // ---- CSR build on side stream, overlapped with layer-1 GEMM ----
    cudaEventRecord(evFork, 0);
    cudaStreamWaitEvent(s2, evFork, 0);
    k_zero<<<32, 1024, 0, s2>>>();
    k_hist<<<N_EDGES / 4 / 256, 256, 0, s2>>>(ei);
    k_scan<<<1, 1024, 0, s2>>>();
    k_scatter<<<N_EDGES / 4 / 256, 256, 0, s2>>>(ei);
    cudaEventRecord(evCsr, s2);

    // ---- layer 1 (GEMM runs concurrently with CSR build) ----
    k_gemm<FT_IN, true><<<N_NODES / 128, 256>>>(x, FT_IN + 1, W1, b1, a1s, a1d);
    cudaStreamWaitEvent(0, evCsr, 0);
    k_gat<0><<<N_NODES / 8, 256>>>();

    // ---- layer 2 (A = tangent buffer, no logmap needed) ----
    k_gemm<HID, false><<<N_NODES / 128, 256>>>(nullptr, HID, W2, b2, a2s, a2d);
    k_gat<1><<<N_NODES / 8, 256>>>();

    // ---- readout (centroid + head fused) ----
    k_readout<<<BATCH, 512>>>(Wl, ls, out);
}

// round 10
// speedup vs baseline: 1.0830x; 1.0830x over previous
#include <cuda_runtime.h>
#include <cuda_fp16.h>
#include <math.h>
#include <stdint.h>

#define N_NODES 32768
#define N_EDGES 524288
#define FT_IN   256
#define HID     128
#define DHID    129        // HID+1
#define BATCH   64
#define NPB     512        // N_NODES / BATCH
#define EPSV    1e-7f

// ---------------- scratch (device globals; no runtime allocation) ----------
__device__ __half2 g_zh[N_NODES * (HID / 2)];  // z in fp16 (gather table)
__device__ float g_ssrc[N_NODES];
__device__ float g_sdst[N_NODES];
__device__ float g_t[N_NODES * HID];      // tangent vec between layers (gelu'd)
__device__ float g_h2[N_NODES * DHID];    // after layer-2 (hyperboloid)
// CSR by dst (built once per call, reused by both layers)
__device__ int   g_off[N_NODES + 1];
__device__ int   g_cur[N_NODES];          // counts, then scatter cursors
__device__ int   g_csrc[N_EDGES];         // src ids grouped by dst

// ---------------- helpers --------------------------------------------------
__device__ __forceinline__ float warp_sum(float v) {
    #pragma unroll
    for (int o = 16; o > 0; o >>= 1) v += __shfl_xor_sync(0xFFFFFFFFu, v, o);
    return v;
}
__device__ __forceinline__ float gelu_tanh(float t) {
    float t3 = t * t * t;
    return 0.5f * t * (1.0f + tanhf(0.7978845608028654f * (t + 0.044715f * t3)));
}
__device__ __forceinline__ uint32_t f2tf32(float f) {
    uint32_t r;
    asm("cvt.rna.tf32.f32 %0, %1;" : "=r"(r) : "f"(f));
    return r;
}
__device__ __forceinline__ void mma_tf32(float c[4], uint32_t a0, uint32_t a1,
                                         uint32_t a2, uint32_t a3,
                                         uint32_t b0, uint32_t b1) {
    asm volatile(
        "mma.sync.aligned.m16n8k8.row.col.f32.tf32.tf32.f32 "
        "{%0,%1,%2,%3}, {%4,%5,%6,%7}, {%8,%9}, {%0,%1,%2,%3};"
        : "+f"(c[0]), "+f"(c[1]), "+f"(c[2]), "+f"(c[3])
        : "r"(a0), "r"(a1), "r"(a2), "r"(a3), "r"(b0), "r"(b1));
}

// ---------------- CSR build -------------------------------------------------
__global__ void k_zero() {
    int i = blockIdx.x * blockDim.x + threadIdx.x;
    if (i < N_NODES) g_cur[i] = 0;
}
__global__ void k_hist(const int* __restrict__ ei) {
    int i = blockIdx.x * blockDim.x + threadIdx.x;     // i < N_EDGES/4
    int4 v = ((const int4*)ei)[i];
    atomicAdd(&g_cur[v.x], 1);
    atomicAdd(&g_cur[v.y], 1);
    atomicAdd(&g_cur[v.z], 1);
    atomicAdd(&g_cur[v.w], 1);
}
// single block, 1024 threads, 32 counts each: exclusive scan -> g_off, g_cur
__global__ void k_scan() {
    __shared__ int bsum[1024];
    int t = threadIdx.x;
    int base = t * 32;
    int local[32];
    int s = 0;
    #pragma unroll
    for (int i = 0; i < 32; i++) { local[i] = g_cur[base + i]; s += local[i]; }
    bsum[t] = s;
    __syncthreads();
    #pragma unroll
    for (int off = 1; off < 1024; off <<= 1) {
        int v = (t >= off) ? bsum[t - off] : 0;
        __syncthreads();
        bsum[t] += v;
        __syncthreads();
    }
    int run = bsum[t] - s;           // exclusive prefix for this thread's chunk
    #pragma unroll
    for (int i = 0; i < 32; i++) {
        g_off[base + i] = run;
        g_cur[base + i] = run;
        run += local[i];
    }
    if (t == 1023) g_off[N_NODES] = run;
}
__global__ void k_scatter(const int* __restrict__ ei) {
    int i = blockIdx.x * blockDim.x + threadIdx.x;     // i < N_EDGES/4
    int4 d = ((const int4*)ei)[i];
    int4 s = ((const int4*)(ei + N_EDGES))[i];
    int p;
    p = atomicAdd(&g_cur[d.x], 1); g_csrc[p] = s.x;
    p = atomicAdd(&g_cur[d.y], 1); g_csrc[p] = s.y;
    p = atomicAdd(&g_cur[d.z], 1); g_csrc[p] = s.z;
    p = atomicAdd(&g_cur[d.w], 1); g_csrc[p] = s.w;
}

// ---------- TF32 MMA GEMM + fused attention scores -------------------------
// LOG=true : A on hyperboloid (lda cols, col0 = time), Z = diag(r)*(Asp@W)+b,
//            r = acosh(max(A0,1+e))/max(||Asp||,e)   (layer 1, A = x)
// LOG=false: A already tangent (g_t, 128 cols), Z = A@W + b (layer 2)
// Emits Z in fp16 (g_zh) and g_ssrc = Z·a_src, g_sdst = Z·a_dst (fp32 exact).
// BM=128, BN=128(HID), BK=16. 256 threads = 8 warps, warp tile 32x64.
template <int K, bool LOG>
__global__ void k_gemm(const float* __restrict__ A, int lda,
                       const float* __restrict__ W,
                       const float* __restrict__ bias,
                       const float* __restrict__ asrc,
                       const float* __restrict__ adst) {
    __shared__ uint32_t As[128][20];   // [m][k] tf32 bits, padded
    __shared__ uint32_t Bs[16][136];   // [k][n] tf32 bits, padded
    __shared__ float    Rs[128];
    __shared__ float    Ssrc[128];
    __shared__ float    Sdst[128];
    const float* Ax = LOG ? A : g_t;
    int t    = threadIdx.x;
    int m0   = blockIdx.x * 128;
    int lane = t & 31, warp = t >> 5;
    int wm = (warp & 3) * 32;          // warp row offset
    int wn = (warp >> 2) * 64;         // warp col offset
    int g  = lane >> 2, tg = lane & 3;

    if (t < 128) { Ssrc[t] = 0.f; Sdst[t] = 0.f; }

    float acc[2][8][4];
    #pragma unroll
    for (int mi = 0; mi < 2; mi++)
        #pragma unroll
        for (int nj = 0; nj < 8; nj++)
            #pragma unroll
            for (int q = 0; q < 4; q++) acc[mi][nj][q] = 0.f;

    int la_m = t >> 1, la_k = (t & 1) * 8;
    int lb_k = t >> 4, lb_n = (t & 15) * 8;
    float ssq = 0.f;

    for (int k0 = 0; k0 < K; k0 += 16) {
        const float* ap = LOG
            ? Ax + (size_t)(m0 + la_m) * lda + 1 + k0 + la_k
            : Ax + (size_t)(m0 + la_m) * HID + k0 + la_k;
        #pragma unroll
        for (int i = 0; i < 8; i++) {
            float v = ap[i];
            if (LOG) ssq += v * v;
            As[la_m][la_k + i] = f2tf32(v);
        }
        const float* bp = W + (size_t)(k0 + lb_k) * HID + lb_n;
        #pragma unroll
        for (int i = 0; i < 8; i++) Bs[lb_k][lb_n + i] = f2tf32(bp[i]);
        __syncthreads();
        #pragma unroll
        for (int ks = 0; ks < 2; ks++) {
            int kk = ks * 8;
            uint32_t bf0[8], bf1[8];
            #pragma unroll
            for (int nj = 0; nj < 8; nj++) {
                bf0[nj] = Bs[kk + tg][wn + nj * 8 + g];
                bf1[nj] = Bs[kk + tg + 4][wn + nj * 8 + g];
            }
            #pragma unroll
            for (int mi = 0; mi < 2; mi++) {
                int r = wm + mi * 16 + g;
                uint32_t a0 = As[r][kk + tg];
                uint32_t a1 = As[r + 8][kk + tg];
                uint32_t a2 = As[r][kk + tg + 4];
                uint32_t a3 = As[r + 8][kk + tg + 4];
                #pragma unroll
                for (int nj = 0; nj < 8; nj++)
                    mma_tf32(acc[mi][nj], a0, a1, a2, a3, bf0[nj], bf1[nj]);
            }
        }
        __syncthreads();
    }
    if (LOG) {
        // per-row logmap0 scale (threads t, t^1 hold halves of row t>>1)
        float tot = ssq + __shfl_xor_sync(0xFFFFFFFFu, ssq, 1);
        if ((t & 1) == 0) {
            float x0 = fmaxf(Ax[(size_t)(m0 + la_m) * lda], 1.0f + EPSV);
            Rs[la_m] = acoshf(x0) / fmaxf(sqrtf(tot), EPSV);
        }
        __syncthreads();
    }

    // epilogue: z = r*acc + bias (fp32), scores fp32, store z as half2
    int   rows[4] = { wm + g, wm + g + 8, wm + 16 + g, wm + 24 + g };
    float rv[4];
    #pragma unroll
    for (int i = 0; i < 4; i++) rv[i] = LOG ? Rs[rows[i]] : 1.0f;
    float ps[4] = {0.f, 0.f, 0.f, 0.f};
    float pd[4] = {0.f, 0.f, 0.f, 0.f};
    #pragma unroll
    for (int nj = 0; nj < 8; nj++) {
        int c = wn + nj * 8 + 2 * tg;
        float b0v = bias[c], b1v = bias[c + 1];
        float s0 = asrc[c], s1 = asrc[c + 1];
        float d0 = adst[c], d1 = adst[c + 1];
        #pragma unroll
        for (int mi = 0; mi < 2; mi++) {
            float r0v = rv[mi * 2], r1v = rv[mi * 2 + 1];
            float v00 = r0v * acc[mi][nj][0] + b0v;
            float v01 = r0v * acc[mi][nj][1] + b1v;
            float v10 = r1v * acc[mi][nj][2] + b0v;
            float v11 = r1v * acc[mi][nj][3] + b1v;
            g_zh[(size_t)(m0 + rows[mi * 2]) * (HID / 2) + (c >> 1)]
                = __floats2half2_rn(v00, v01);
            g_zh[(size_t)(m0 + rows[mi * 2 + 1]) * (HID / 2) + (c >> 1)]
                = __floats2half2_rn(v10, v11);
            ps[mi * 2]     += v00 * s0 + v01 * s1;
            ps[mi * 2 + 1] += v10 * s0 + v11 * s1;
            pd[mi * 2]     += v00 * d0 + v01 * d1;
            pd[mi * 2 + 1] += v10 * d0 + v11 * d1;
        }
    }
    #pragma unroll
    for (int i = 0; i < 4; i++) {
        atomicAdd(&Ssrc[rows[i]], ps[i]);
        atomicAdd(&Sdst[rows[i]], pd[i]);
    }
    __syncthreads();
    if (t < 128) {
        g_ssrc[m0 + t] = Ssrc[t];
        g_sdst[m0 + t] = Sdst[t];
    }
}

// ---------------- fused GAT aggregation + post-processing -------------------
// One warp per node; lane l owns channels [4l, 4l+4).
// Per 32-edge chunk: coalesced csrc load + per-lane score/exp, then shfl
// distributes (src, w); z-gathers are the only per-edge memory ops.
// No softmax max-shift (scores O(0.01), exp cannot overflow).
//  MODE 0: g = gelu(logmap0(projx(expmap0(u))))  -> g_t  (tangent; the
//          expmap0 for layer-2 input cancels against its logmap0 exactly)
//  MODE 1: h = projx(expmap0(u))                 -> g_h2
template <int MODE>
__global__ void k_gat() {
    int node = blockIdx.x * 8 + (threadIdx.x >> 5);
    int lane = threadIdx.x & 31;
    int beg = g_off[node], end = g_off[node + 1];
    float sdst = g_sdst[node];
    float4 acc = make_float4(0.f, 0.f, 0.f, 0.f);
    float denp = 0.f;

    for (int base = beg; base < end; base += 32) {
        int m = end - base; if (m > 32) m = 32;
        int sid = 0; float w = 0.f;
        if (lane < m) {
            sid = g_csrc[base + lane];
            float sc = sdst + g_ssrc[sid];
            sc = (sc > 0.f) ? sc : 0.2f * sc;
            w = __expf(sc);
        }
        denp += w;
        int j = 0;
        for (; j + 4 <= m; j += 4) {
            int s0 = __shfl_sync(0xFFFFFFFFu, sid, j);
            int s1 = __shfl_sync(0xFFFFFFFFu, sid, j + 1);
            int s2 = __shfl_sync(0xFFFFFFFFu, sid, j + 2);
            int s3 = __shfl_sync(0xFFFFFFFFu, sid, j + 3);
            float w0 = __shfl_sync(0xFFFFFFFFu, w, j);
            float w1 = __shfl_sync(0xFFFFFFFFu, w, j + 1);
            float w2 = __shfl_sync(0xFFFFFFFFu, w, j + 2);
            float w3 = __shfl_sync(0xFFFFFFFFu, w, j + 3);
            uint2 p0 = ((const uint2*)(g_zh + (size_t)s0 * (HID / 2)))[lane];
            uint2 p1 = ((const uint2*)(g_zh + (size_t)s1 * (HID / 2)))[lane];
            uint2 p2 = ((const uint2*)(g_zh + (size_t)s2 * (HID / 2)))[lane];
            uint2 p3 = ((const uint2*)(g_zh + (size_t)s3 * (HID / 2)))[lane];
            float2 a0 = __half22float2(*(const __half2*)&p0.x);
            float2 b0 = __half22float2(*(const __half2*)&p0.y);
            float2 a1 = __half22float2(*(const __half2*)&p1.x);
            float2 b1 = __half22float2(*(const __half2*)&p1.y);
            float2 a2 = __half22float2(*(const __half2*)&p2.x);
            float2 b2 = __half22float2(*(const __half2*)&p2.y);
            float2 a3 = __half22float2(*(const __half2*)&p3.x);
            float2 b3 = __half22float2(*(const __half2*)&p3.y);
            acc.x += w0 * a0.x + w1 * a1.x + w2 * a2.x + w3 * a3.x;
            acc.y += w0 * a0.y + w1 * a1.y + w2 * a2.y + w3 * a3.y;
            acc.z += w0 * b0.x + w1 * b1.x + w2 * b2.x + w3 * b3.x;
            acc.w += w0 * b0.y + w1 * b1.y + w2 * b2.y + w3 * b3.y;
        }
        for (; j < m; j++) {
            int sj = __shfl_sync(0xFFFFFFFFu, sid, j);
            float wj = __shfl_sync(0xFFFFFFFFu, w, j);
            uint2 pj = ((const uint2*)(g_zh + (size_t)sj * (HID / 2)))[lane];
            float2 aj = __half22float2(*(const __half2*)&pj.x);
            float2 bj = __half22float2(*(const __half2*)&pj.y);
            acc.x += wj * aj.x; acc.y += wj * aj.y;
            acc.z += wj * bj.x; acc.w += wj * bj.y;
        }
    }
    float den = warp_sum(denp);

    float dn = fmaxf(den, EPSV);
    float u[4] = { acc.x / dn, acc.y / dn, acc.z / dn, acc.w / dn };
    float ss = u[0]*u[0] + u[1]*u[1] + u[2]*u[2] + u[3]*u[3];
    ss = warp_sum(ss);
    float n    = sqrtf(ss);
    float coef = (n < EPSV) ? 1.0f : (sinhf(n) / n);      // expmap0 spatial

    float xs_n2 = coef * coef * ss;
    if (MODE == 1) {
        float* hr = g_h2 + (size_t)node * DHID;
        if (lane == 0) hr[0] = sqrtf(1.0f + xs_n2);
        #pragma unroll
        for (int q = 0; q < 4; q++) hr[1 + lane * 4 + q] = coef * u[q];
        return;
    }
    // MODE 0: projx -> logmap0 -> gelu, store tangent vector (no expmap0:
    // it cancels against layer-2's logmap0)
    float x0p = sqrtf(1.0f + xs_n2);
    float xsn = sqrtf(xs_n2);
    float sc2 = acoshf(fmaxf(x0p, 1.0f + EPSV)) / fmaxf(xsn, EPSV);
    float4 gv;
    gv.x = gelu_tanh(sc2 * coef * u[0]);
    gv.y = gelu_tanh(sc2 * coef * u[1]);
    gv.z = gelu_tanh(sc2 * coef * u[2]);
    gv.w = gelu_tanh(sc2 * coef * u[3]);
    ((float4*)(g_t + (size_t)node * HID))[lane] = gv;
}

// --------- fused centroid + head (one block per batch graph) ----------------
// Block b (256 threads, 8 warps): warp w register-accumulates rows w, w+8, ...
// of the contiguous 512x129 slab (lane owns 5 columns), combines via smem
// (no atomics), then centroid-normalize + W_lin head in the same block.
__global__ void k_readout(const float* __restrict__ Wl,
                          const float* __restrict__ lin_scale,
                          float* __restrict__ out) {
    int b = blockIdx.x;
    int t = threadIdx.x;
    int warp = t >> 5, lane = t & 31;
    __shared__ float accs[8][DHID + 3];    // per-warp column partials (padded)
    __shared__ float ave[DHID];
    __shared__ float gsh[DHID];
    __shared__ float red[3];

    const float* base = g_h2 + (size_t)b * NPB * DHID;
    float ra[5] = {0.f, 0.f, 0.f, 0.f, 0.f};
    for (int r = warp; r < NPB; r += 8) {
        const float* row = base + (size_t)r * DHID;
        #pragma unroll
        for (int q = 0; q < 5; q++) {
            int c = lane + 32 * q;
            if (c < DHID) ra[q] += row[c];
        }
    }
    #pragma unroll
    for (int q = 0; q < 5; q++) {
        int c = lane + 32 * q;
        if (c < DHID) accs[warp][c] = ra[q];
    }
    __syncthreads();
    if (t < DHID) {
        float s = 0.f;
        #pragma unroll
        for (int w = 0; w < 8; w++) s += accs[w][t];
        ave[t] = s * (1.0f / (float)NPB);
        gsh[t] = base[t];                  // node b*512 row (for head)
    }
    __syncthreads();

    if (t == 0) {
        float inner = 0.f;
        #pragma unroll 4
        for (int c = 1; c < DHID; c++) inner += ave[c] * ave[c];
        inner -= ave[0] * ave[0];
        red[0] = sqrtf(fmaxf(-inner, 1e-8f));
    }
    __syncthreads();
    if (t < DHID)
        out[BATCH * DHID + b * DHID + t] = ave[t] / red[0];

    // ---- head ----
    float y = 0.f;
    if (t < DHID) {
        #pragma unroll 4
        for (int k = 0; k < DHID; k++) y += gsh[k] * Wl[k * DHID + t];
    }
    if (t == 0) { red[1] = y; red[2] = 0.f; }
    __syncthreads();
    if (t >= 1 && t < DHID) atomicAdd(&red[2], y * y);
    __syncthreads();
    if (t < DHID) {
        float tt  = 1.0f / (1.0f + expf(-red[1])) * lin_scale[0] + 1.1f;
        float fac = sqrtf((tt * tt - 1.0f) / fmaxf(red[2], 1e-8f));
        out[b * DHID + t] = (t == 0) ? tt : y * fac;
    }
}

// ---------------- launch ----------------------------------------------------
extern "C" void kernel_launch(void* const* d_in, const int* in_sizes, int n_in,
                              void* d_out, int out_size) {
    int idx = 0;
    const float* x  = (const float*)d_in[idx++];   // (32768, 257)
    const int*   ei = (const int*)d_in[idx++];     // (2, 524288)
    if (idx < n_in && in_sizes[idx] == 1) idx++;   // batch_size scalar, if present
    const float* W1  = (const float*)d_in[idx++];
    const float* b1  = (const float*)d_in[idx++];
    const float* a1s = (const float*)d_in[idx++];
    const float* a1d = (const float*)d_in[idx++];
    const float* W2  = (const float*)d_in[idx++];
    const float* b2  = (const float*)d_in[idx++];
    const float* a2s = (const float*)d_in[idx++];
    const float* a2d = (const float*)d_in[idx++];
    const float* Wl  = (const float*)d_in[idx++];
    const float* ls  = (const float*)d_in[idx++];
    float* out = (float*)d_out;

    // side stream + events, created once (first call is the uncaptured
    // correctness run; capture replays see only the recorded DAG)
    static cudaStream_t s2 = 0;
    static cudaEvent_t evFork = 0, evCsr = 0;
    if (!s2) {
        cudaStreamCreateWithFlags(&s2, cudaStreamNonBlocking);
        cudaEventCreateWithFlags(&evFork, cudaEventDisableTiming);
        cudaEventCreateWithFlags(&evCsr, cudaEventDisableTiming);
    }

    // ---- CSR build on side stream, overlapped with layer-1 GEMM ----
    cudaEventRecord(evFork, 0);
    cudaStreamWaitEvent(s2, evFork, 0);
    k_zero<<<32, 1024, 0, s2>>>();
    k_hist<<<N_EDGES / 4 / 256, 256, 0, s2>>>(ei);
    k_scan<<<1, 1024, 0, s2>>>();
    k_scatter<<<N_EDGES / 4 / 256, 256, 0, s2>>>(ei);
    cudaEventRecord(evCsr, s2);

    // ---- layer 1 (GEMM runs concurrently with CSR build) ----
    k_gemm<FT_IN, true><<<N_NODES / 128, 256>>>(x, FT_IN + 1, W1, b1, a1s, a1d);
    cudaStreamWaitEvent(0, evCsr, 0);
    k_gat<0><<<N_NODES / 8, 256>>>();

    // ---- layer 2 (A = tangent buffer, no logmap needed) ----
    k_gemm<HID, false><<<N_NODES / 128, 256>>>(nullptr, HID, W2, b2, a2s, a2d);
    k_gat<1><<<N_NODES / 8, 256>>>();

    // ---- readout (centroid + head fused, no smem atomics) ----
    k_readout<<<BATCH, 256>>>(Wl, ls, out);
}